// round 2
// baseline (speedup 1.0000x reference)
#include <cuda_runtime.h>
#include <cstdint>

// DCT_Layer: grouped conv with fixed separable 4x4 DCT basis, padding=2,
// then min(|v|, 8).
// x: (8, 3, 512, 512) f32  ->  out: (8, 48, 513, 513) f32
//
// Separable: k[kk*4+ll][i][j] = A[kk][i] * A[ll][j]
//   A[0] = {.5,.5,.5,.5}
//   A[1] = { a, b,-b,-a}   a=0.653281..., b=0.270598...
//   A[2] = {.5,-.5,-.5,.5}
//   A[3] = { b,-a, a,-b}

#define HIN   512
#define WIN   512
#define HOUT  513
#define WOUT  513
#define PLANE (HOUT * WOUT)   // 263169
#define TX    128             // output columns per block
#define RY    4               // output rows per block
#define NROW  (RY + 3)        // input rows needed: 7
#define NCOL  (TX + 3)        // input cols needed: 131
#define NCOLP (TX + 4)        // padded

#define CA 0.65328148243818826f
#define CB 0.27059805007309851f

__global__ __launch_bounds__(TX, 8)
void dct_layer_kernel(const float* __restrict__ x, float* __restrict__ out) {
    const int bc    = blockIdx.z;            // b*3 + c (0..23)
    const int y0    = blockIdx.y * RY;       // first output row of this block
    const int xbase = blockIdx.x * TX;       // output col base
    const int t     = threadIdx.x;

    __shared__ float xin[NROW][NCOLP];       // 7 input rows
    __shared__ float s[RY][4][NCOLP];        // column-DCT per output row, per kk

    const float* __restrict__ xp = x + (size_t)bc * (HIN * WIN);

    // ---- cooperative load: input rows y0-2 .. y0+RY, cols xbase-2 .. xbase+TX
    for (int idx = t; idx < NROW * NCOL; idx += TX) {
        int i  = idx / NCOL;
        int xi = idx - i * NCOL;
        int iy = y0 - 2 + i;
        int ix = xbase - 2 + xi;
        float v = 0.0f;
        if ((unsigned)iy < (unsigned)HIN && (unsigned)ix < (unsigned)WIN)
            v = xp[iy * WIN + ix];
        xin[i][xi] = v;
    }
    __syncthreads();

    // ---- column pass: for each output row r, s[r][kk][xi] = sum_i A[kk][i]*xin[r+i][xi]
    for (int xi = t; xi < NCOL; xi += TX) {
        float v0 = xin[0][xi], v1 = xin[1][xi], v2 = xin[2][xi], v3 = xin[3][xi];
        float v4 = xin[4][xi], v5 = xin[5][xi], v6 = xin[6][xi];
#pragma unroll
        for (int r = 0; r < RY; r++) {
            float a0, a1, a2, a3;
            switch (r) {
                case 0: a0 = v0; a1 = v1; a2 = v2; a3 = v3; break;
                case 1: a0 = v1; a1 = v2; a2 = v3; a3 = v4; break;
                case 2: a0 = v2; a1 = v3; a2 = v4; a3 = v5; break;
                default: a0 = v3; a1 = v4; a2 = v5; a3 = v6; break;
            }
            float p = a0 + a3, q = a1 + a2;
            float m = a0 - a3, n = a1 - a2;
            s[r][0][xi] = 0.5f * (p + q);
            s[r][1][xi] = CA * m + CB * n;
            s[r][2][xi] = 0.5f * (p - q);
            s[r][3][xi] = CB * m - CA * n;
        }
    }
    __syncthreads();

    // ---- row pass + clamp + store
    const int xo = xbase + t;
    if (xo < WOUT) {
        float* __restrict__ base = out + (size_t)bc * (16 * (size_t)PLANE)
                                       + (size_t)y0 * WOUT + xo;
#pragma unroll
        for (int r = 0; r < RY; r++) {
            const int y = y0 + r;
            if (y >= HOUT) break;
            float* __restrict__ op = base + (size_t)r * WOUT;
#pragma unroll
            for (int kk = 0; kk < 4; kk++) {
                float s0 = s[r][kk][t + 0];
                float s1 = s[r][kk][t + 1];
                float s2 = s[r][kk][t + 2];
                float s3 = s[r][kk][t + 3];
                float p = s0 + s3, q = s1 + s2;
                float m = s0 - s3, n = s1 - s2;
                float r0 = 0.5f * (p + q);
                float r1 = CA * m + CB * n;
                float r2 = 0.5f * (p - q);
                float r3 = CB * m - CA * n;
                op[(size_t)(kk * 4 + 0) * PLANE] = fminf(fabsf(r0), 8.0f);
                op[(size_t)(kk * 4 + 1) * PLANE] = fminf(fabsf(r1), 8.0f);
                op[(size_t)(kk * 4 + 2) * PLANE] = fminf(fabsf(r2), 8.0f);
                op[(size_t)(kk * 4 + 3) * PLANE] = fminf(fabsf(r3), 8.0f);
            }
        }
    }
}

extern "C" void kernel_launch(void* const* d_in, const int* in_sizes, int n_in,
                              void* d_out, int out_size) {
    const float* x  = (const float*)d_in[0];
    float* out      = (float*)d_out;
    (void)in_sizes; (void)n_in; (void)out_size;

    dim3 grid((WOUT + TX - 1) / TX,        // 5
              (HOUT + RY - 1) / RY,        // 129
              8 * 3);                      // 24
    dim3 block(TX);
    dct_layer_kernel<<<grid, block>>>(x, out);
}

// round 3
// speedup vs baseline: 1.2656x; 1.2656x over previous
#include <cuda_runtime.h>
#include <cstdint>

// DCT_Layer: grouped conv, fixed separable 4x4 DCT basis, pad=2, min(|v|,8).
// x: (8,3,512,512) f32 -> out: (8,48,513,513) f32
//
// A[0]={.5,.5,.5,.5}; A[1]={a,b,-b,-a}; A[2]={.5,-.5,-.5,.5}; A[3]={b,-a,a,-b}

#define HIN   512
#define WIN   512
#define HOUT  513
#define WOUT  513
#define PLANE (HOUT * WOUT)    // 263169  (== 1 mod 4 !)
#define NT    128
#define NCOL  516              // input cols -2..513 (s-index = input col + 2)
#define SPITCH 136             // padded: banks 8j+q cover all 32 -> conflict-free

#define CA 0.65328148243818826f
#define CB 0.27059805007309851f

__constant__ float c_A[4][4] = {
    { 0.5f,  0.5f,  0.5f,  0.5f },
    {  CA,    CB,   -CB,   -CA  },
    { 0.5f, -0.5f, -0.5f,  0.5f },
    {  CB,   -CA,    CA,   -CB  }
};

// row-DCT of a 4-window for basis row ll; ll is a literal after unroll
__device__ __forceinline__ float rowv(int ll, float a, float b, float c, float d) {
    if (ll == 0) return 0.5f * ((a + d) + (b + c));
    if (ll == 1) return CA * (a - d) + CB * (b - c);
    if (ll == 2) return 0.5f * ((a + d) - (b + c));
    return CB * (a - d) - CA * (b - c);
}

__device__ __forceinline__ float trunc8(float v) { return fminf(fabsf(v), 8.0f); }

__global__ __launch_bounds__(NT, 8)
void dct_layer_kernel(const float* __restrict__ x, float* __restrict__ out) {
    const int y  = blockIdx.x;     // output row 0..512
    const int bc = blockIdx.y;     // b*3+c, 0..23
    const int t  = threadIdx.x;

    __shared__ float xin[4][NCOL + 4];
    __shared__ float st[4][4][SPITCH];   // [kk][ci&3][ci>>2]

    const float* __restrict__ xp = x + (size_t)bc * (HIN * WIN);

    // ---- cooperative load: input rows y-2..y+1, cols -2..513
    for (int idx = t; idx < 4 * NCOL; idx += NT) {
        int i  = idx / NCOL;
        int ci = idx - i * NCOL;
        int iy = y - 2 + i;
        int ix = ci - 2;
        float v = 0.0f;
        if ((unsigned)iy < (unsigned)HIN && (unsigned)ix < (unsigned)WIN)
            v = xp[iy * WIN + ix];
        xin[i][ci] = v;
    }
    __syncthreads();

    // ---- column pass into transposed conflict-free layout
    for (int ci = t; ci < NCOL; ci += NT) {
        float v0 = xin[0][ci], v1 = xin[1][ci], v2 = xin[2][ci], v3 = xin[3][ci];
        float p = v0 + v3, q = v1 + v2;
        float m = v0 - v3, n = v1 - v2;
        int j = ci & 3, c4 = ci >> 2;
        st[0][j][c4] = 0.5f * (p + q);
        st[1][j][c4] = CA * m + CB * n;
        st[2][j][c4] = 0.5f * (p - q);
        st[3][j][c4] = CB * m - CA * n;
    }
    __syncthreads();

    // ---- row pass: per plane p, aligned float4 streaming stores + edges
    float* __restrict__ ob = out + (size_t)(bc * 16) * PLANE + (size_t)y * WOUT;

#pragma unroll
    for (int p = 0; p < 16; p++) {
        const int kk = p >> 2, ll = p & 3;
        // choose c0 = shift + 4t so that (bc*16+p)*PLANE + y*513 + c0 == 0 mod 4
        const int shift = (4 - ((y + p) & 3)) & 3;
        const int np = (WOUT - shift) >> 2;          // 127 or 128 float4 groups
        float* __restrict__ op = ob + (size_t)p * PLANE;

        if (t < np) {
            const int c0 = shift + 4 * t;
            float w[7];
#pragma unroll
            for (int u = 0; u < 7; u++)
                w[u] = st[kk][(c0 + u) & 3][(c0 + u) >> 2];
            float4 v;
            v.x = trunc8(rowv(ll, w[0], w[1], w[2], w[3]));
            v.y = trunc8(rowv(ll, w[1], w[2], w[3], w[4]));
            v.z = trunc8(rowv(ll, w[2], w[3], w[4], w[5]));
            v.w = trunc8(rowv(ll, w[3], w[4], w[5], w[6]));
            __stcs(reinterpret_cast<float4*>(op + c0), v);
        }

        // edge columns: [0,shift) and [shift+4*np, 513)  (1 or 5 columns total)
        const int rs = shift + 4 * np;
        const int ne_l = shift;
        const int ne = ne_l + (WOUT - rs);
        if (t < ne) {
            const int c = (t < ne_l) ? t : (rs + t - ne_l);
            float w0 = st[kk][(c + 0) & 3][(c + 0) >> 2];
            float w1 = st[kk][(c + 1) & 3][(c + 1) >> 2];
            float w2 = st[kk][(c + 2) & 3][(c + 2) >> 2];
            float w3 = st[kk][(c + 3) & 3][(c + 3) >> 2];
            float r = c_A[ll][0] * w0 + c_A[ll][1] * w1
                    + c_A[ll][2] * w2 + c_A[ll][3] * w3;
            op[c] = trunc8(r);
        }
    }
}

extern "C" void kernel_launch(void* const* d_in, const int* in_sizes, int n_in,
                              void* d_out, int out_size) {
    const float* x = (const float*)d_in[0];
    float* out     = (float*)d_out;
    (void)in_sizes; (void)n_in; (void)out_size;

    dim3 grid(HOUT, 8 * 3);   // (513, 24)
    dim3 block(NT);
    dct_layer_kernel<<<grid, block>>>(x, out);
}

// round 4
// speedup vs baseline: 1.2760x; 1.0082x over previous
#include <cuda_runtime.h>
#include <cstdint>

// DCT_Layer: grouped conv, fixed separable 4x4 DCT basis, pad=2, min(|v|,8).
// x: (8,3,512,512) f32 -> out: (8,48,513,513) f32
//
// Separable: k[kk*4+ll][i][j] = A[kk][i]*A[ll][j]
//   A[0]={.5,.5,.5,.5}; A[1]={a,b,-b,-a}; A[2]={.5,-.5,-.5,.5}; A[3]={b,-a,a,-b}
// Column scale (0.5 for even kk) is folded into the row-pass coefficients.

#define HIN   512
#define WIN   512
#define HOUT  513
#define WOUT  513
#define PLANE (HOUT * WOUT)   // 263169 (== 1 mod 4)
#define NT    128
#define XCOL  520             // s-cols 0..519 (input col = s-col - 2); 520/4=130 float4
#define CA 0.65328148243818826f
#define CB 0.27059805007309851f

__device__ __forceinline__ float t8(float v) { return fminf(fabsf(v), 8.0f); }

// read 10 floats of smem row starting at col 4t (3 conflict-free LDS.128)
__device__ __forceinline__ void load10(const float4* __restrict__ xr, int rowbase4,
                                       int t, float* __restrict__ r) {
    float4 a = xr[rowbase4 + t];
    float4 b = xr[rowbase4 + t + 1];
    float4 c = xr[rowbase4 + t + 2];
    r[0]=a.x; r[1]=a.y; r[2]=a.z; r[3]=a.w;
    r[4]=b.x; r[5]=b.y; r[6]=b.z; r[7]=b.w;
    r[8]=c.x; r[9]=c.y;
}

// One output plane (kk fixed by caller via s/HALF, ll = LL, column shift = SH).
// s[j] = (unscaled for even kk) column-DCT at s-col 4t+j.
// g[j] = s[j]-s[j+1], e[j] = s[j]-s[j+3].
// plane = out + plane_offset + y*513 + 4t.
template<int SH, int LL, bool HALF>
__device__ __forceinline__ void do_plane(const float* __restrict__ s,
                                         const float* __restrict__ g,
                                         const float* __restrict__ e,
                                         float* __restrict__ plane, int t) {
    const float h  = HALF ? 0.5f : 1.0f;
    const float q0 = 0.5f * h;
    const float qa = CA * h, qb = CB * h;

    float4 v;
    if (LL == 0) {
        float S = (s[SH] + s[SH+1]) + (s[SH+2] + s[SH+3]);
        v.x = t8(q0 * S);
        S += s[SH+4] - s[SH+0];  v.y = t8(q0 * S);
        S += s[SH+5] - s[SH+1];  v.z = t8(q0 * S);
        S += s[SH+6] - s[SH+2];  v.w = t8(q0 * S);
    } else if (LL == 1) {
        v.x = t8(qa * e[SH+0] + qb * g[SH+1]);
        v.y = t8(qa * e[SH+1] + qb * g[SH+2]);
        v.z = t8(qa * e[SH+2] + qb * g[SH+3]);
        v.w = t8(qa * e[SH+3] + qb * g[SH+4]);
    } else if (LL == 2) {
        v.x = t8(q0 * (g[SH+0] - g[SH+2]));
        v.y = t8(q0 * (g[SH+1] - g[SH+3]));
        v.z = t8(q0 * (g[SH+2] - g[SH+4]));
        v.w = t8(q0 * (g[SH+3] - g[SH+5]));
    } else {
        v.x = t8(qb * e[SH+0] - qa * g[SH+1]);
        v.y = t8(qb * e[SH+1] - qa * g[SH+2]);
        v.z = t8(qb * e[SH+2] - qa * g[SH+3]);
        v.w = t8(qb * e[SH+3] - qa * g[SH+4]);
    }
    if (SH <= 1 || t < NT - 1)
        __stcs(reinterpret_cast<float4*>(plane + SH), v);

    // left edge: cols 0..SH-1, handled by thread 0 (its s[] starts at col 0)
    if (SH > 0 && t == 0) {
#pragma unroll
        for (int c = 0; c < SH; c++) {
            float r;
            if (LL == 0)      r = q0 * ((s[c] + s[c+1]) + (s[c+2] + s[c+3]));
            else if (LL == 1) r = qa * e[c] + qb * g[c+1];
            else if (LL == 2) r = q0 * (g[c] - g[c+2]);
            else              r = qb * e[c] - qa * g[c+1];
            plane[c] = t8(r);
        }
    }
    // right edge: cols RS..512, handled by thread 127 (its s[] starts at col 508)
    {
        constexpr int NP = (WOUT - SH) >> 2;
        constexpr int RS = SH + 4 * NP;
        if (RS < WOUT && t == NT - 1) {
#pragma unroll
            for (int c = RS; c < WOUT; c++) {
                constexpr int B = 4 * (NT - 1);
                const int j = c - B;   // compile-time after unroll
                float r;
                if (LL == 0)      r = q0 * ((s[j] + s[j+1]) + (s[j+2] + s[j+3]));
                else if (LL == 1) r = qa * e[j] + qb * g[j+1];
                else if (LL == 2) r = q0 * (g[j] - g[j+2]);
                else              r = qb * e[j] - qa * g[j+1];
                plane[j] = t8(r);
            }
        }
    }
}

// 4 planes (ll=0..3) of one kk
template<int S0, int S1, int S2, int S3, bool HALF>
__device__ __forceinline__ void quad(const float* __restrict__ s,
                                     float* __restrict__ pb, int t) {
    float g[9], e[7];
#pragma unroll
    for (int j = 0; j < 9; j++) g[j] = s[j] - s[j+1];
#pragma unroll
    for (int j = 0; j < 7; j++) e[j] = s[j] - s[j+3];
    do_plane<S0, 0, HALF>(s, g, e, pb,             t);
    do_plane<S1, 1, HALF>(s, g, e, pb + 1 * PLANE, t);
    do_plane<S2, 2, HALF>(s, g, e, pb + 2 * PLANE, t);
    do_plane<S3, 3, HALF>(s, g, e, pb + 3 * PLANE, t);
}

template<int YM>
__device__ __forceinline__ void tail(const float4* __restrict__ xr,
                                     float* __restrict__ pb, int t) {
    constexpr int S0 = (4 - ((YM + 0) & 3)) & 3;
    constexpr int S1 = (4 - ((YM + 1) & 3)) & 3;
    constexpr int S2 = (4 - ((YM + 2) & 3)) & 3;
    constexpr int S3 = (4 - ((YM + 3) & 3)) & 3;

    float A[10], B[10], P[10], Q[10], s[10];

    // even kk: sums
    load10(xr,   0, t, A);            // row 0
    load10(xr, 390, t, B);            // row 3
#pragma unroll
    for (int j = 0; j < 10; j++) P[j] = A[j] + B[j];
    load10(xr, 130, t, A);            // row 1
    load10(xr, 260, t, B);            // row 2
#pragma unroll
    for (int j = 0; j < 10; j++) Q[j] = A[j] + B[j];

#pragma unroll
    for (int j = 0; j < 10; j++) s[j] = P[j] + Q[j];
    quad<S0, S1, S2, S3, true>(s, pb, t);                       // kk = 0
#pragma unroll
    for (int j = 0; j < 10; j++) s[j] = P[j] - Q[j];
    quad<S0, S1, S2, S3, true>(s, pb + 8 * PLANE, t);           // kk = 2

    // odd kk: diffs (reload rows to keep register pressure down)
    load10(xr,   0, t, A);
    load10(xr, 390, t, B);
#pragma unroll
    for (int j = 0; j < 10; j++) P[j] = A[j] - B[j];            // M
    load10(xr, 130, t, A);
    load10(xr, 260, t, B);
#pragma unroll
    for (int j = 0; j < 10; j++) Q[j] = A[j] - B[j];            // N

#pragma unroll
    for (int j = 0; j < 10; j++) s[j] = CA * P[j] + CB * Q[j];
    quad<S0, S1, S2, S3, false>(s, pb + 4 * PLANE, t);          // kk = 1
#pragma unroll
    for (int j = 0; j < 10; j++) s[j] = CB * P[j] - CA * Q[j];
    quad<S0, S1, S2, S3, false>(s, pb + 12 * PLANE, t);         // kk = 3
}

__global__ __launch_bounds__(NT, 8)
void dct_layer_kernel(const float* __restrict__ x, float* __restrict__ out) {
    const int y  = blockIdx.x;      // 0..512
    const int bc = blockIdx.y;      // 0..23
    const int t  = threadIdx.x;

    __shared__ float xin[4][XCOL];  // zero-padded input window, pitch 2080B (16B mult)

    const float* __restrict__ xp = x + (size_t)bc * (HIN * WIN);
#pragma unroll
    for (int i = 0; i < 4; i++) {
        const int iy = y - 2 + i;
        const bool rok = (unsigned)iy < (unsigned)HIN;
        const float* __restrict__ rp = xp + iy * WIN;
        for (int c = t; c < XCOL; c += NT) {
            const int ix = c - 2;
            xin[i][c] = (rok && (unsigned)ix < (unsigned)WIN) ? rp[ix] : 0.0f;
        }
    }
    __syncthreads();

    float* __restrict__ pb = out + (size_t)(bc * 16) * PLANE + y * WOUT + 4 * t;
    const float4* __restrict__ xr = reinterpret_cast<const float4*>(&xin[0][0]);

    switch (y & 3) {
        case 0: tail<0>(xr, pb, t); break;
        case 1: tail<1>(xr, pb, t); break;
        case 2: tail<2>(xr, pb, t); break;
        default: tail<3>(xr, pb, t); break;
    }
}

extern "C" void kernel_launch(void* const* d_in, const int* in_sizes, int n_in,
                              void* d_out, int out_size) {
    const float* x = (const float*)d_in[0];
    float* out     = (float*)d_out;
    (void)in_sizes; (void)n_in; (void)out_size;

    dim3 grid(HOUT, 8 * 3);   // (513, 24)
    dim3 block(NT);
    dct_layer_kernel<<<grid, block>>>(x, out);
}

// round 5
// speedup vs baseline: 1.4490x; 1.1356x over previous
#include <cuda_runtime.h>
#include <cstdint>

// DCT_Layer: grouped conv, fixed separable 4x4 DCT basis, pad=2, min(|v|,8).
// x: (8,3,512,512) f32 -> out: (8,48,513,513) f32
//
// Block = 512 threads = 4 groups of 128. Column DCT computed once into smem;
// group kk produces planes kk*4+ll (ll=0..3) with aligned float4 stores.
//   A[0]={.5,.5,.5,.5}; A[1]={a,b,-b,-a}; A[2]={.5,-.5,-.5,.5}; A[3]={b,-a,a,-b}

#define HIN   512
#define WIN   512
#define HOUT  513
#define WOUT  513
#define PLANE (HOUT * WOUT)   // 263169 (== 1 mod 4)
#define XCOL  520             // s-cols 0..519; input col = s-col - 2
#define CA 0.65328148243818826f
#define CB 0.27059805007309851f

__device__ __forceinline__ float t8(float v) { return fminf(fabsf(v), 8.0f); }

// 4-tap row DCT at window offset c (c compile-time after unroll)
template<int LL>
__device__ __forceinline__ float rowdct(const float* __restrict__ w, int c) {
    if (LL == 0) return 0.5f * ((w[c] + w[c+1]) + (w[c+2] + w[c+3]));
    if (LL == 1) return CA * (w[c] - w[c+3]) + CB * (w[c+1] - w[c+2]);
    if (LL == 2) return 0.5f * ((w[c] + w[c+3]) - (w[c+1] + w[c+2]));
    return CB * (w[c] - w[c+3]) - CA * (w[c+1] - w[c+2]);
}

// One plane: aligned float4 main store + edge columns.
// pl = plane base + y*513 + 4*tt. Thread tt's window w[] = s-cols 4tt..4tt+11.
template<int SH, int LL>
__device__ __forceinline__ void plane_out(const float* __restrict__ w,
                                          float* __restrict__ pl, int tt) {
    float4 v;
    v.x = t8(rowdct<LL>(w, SH + 0));
    v.y = t8(rowdct<LL>(w, SH + 1));
    v.z = t8(rowdct<LL>(w, SH + 2));
    v.w = t8(rowdct<LL>(w, SH + 3));
    if (SH <= 1 || tt < 127)
        __stcs(reinterpret_cast<float4*>(pl + SH), v);

    // left edge: cols 0..SH-1 (thread 0's window starts at col 0)
    if (SH > 0 && tt == 0) {
#pragma unroll
        for (int c = 0; c < SH; c++)
            pl[c] = t8(rowdct<LL>(w, c));
    }
    // right edge: cols RS..512 (thread 127's window starts at col 508)
    constexpr int NP = (WOUT - SH) >> 2;
    constexpr int RS = SH + 4 * NP;
    if (RS < WOUT && tt == 127) {
#pragma unroll
        for (int c = RS; c < WOUT; c++)
            pl[c - 508] = t8(rowdct<LL>(w, c - 508));
    }
}

template<int YM>
__device__ __forceinline__ void tail(const float* __restrict__ w,
                                     float* __restrict__ pb, int tt) {
    plane_out<(4 - ((YM + 0) & 3)) & 3, 0>(w, pb,                    tt);
    plane_out<(4 - ((YM + 1) & 3)) & 3, 1>(w, pb + 1 * (size_t)PLANE, tt);
    plane_out<(4 - ((YM + 2) & 3)) & 3, 2>(w, pb + 2 * (size_t)PLANE, tt);
    plane_out<(4 - ((YM + 3) & 3)) & 3, 3>(w, pb + 3 * (size_t)PLANE, tt);
}

__global__ __launch_bounds__(512, 3)
void dct_layer_kernel(const float* __restrict__ x, float* __restrict__ out) {
    const int y  = blockIdx.x;     // 0..512
    const int bc = blockIdx.y;     // 0..23
    const int t  = threadIdx.x;

    __shared__ float xin[4][XCOL];  // raw input window (pitch 2080B, 16B mult)
    __shared__ float sc[4][XCOL];   // column DCT per kk

    const float* __restrict__ xp = x + (size_t)bc * (HIN * WIN);

    // ---- load: one predicated LDG.128 per thread (row = t>>7, 4 cols = 4*(t&127))
    {
        const int row = t >> 7, j = t & 127;
        const int iy = y - 2 + row;
        float4 v = make_float4(0.f, 0.f, 0.f, 0.f);
        if ((unsigned)iy < (unsigned)HIN)
            v = *reinterpret_cast<const float4*>(xp + iy * WIN + 4 * j);
        float* xr = &xin[row][2 + 4 * j];
        xr[0] = v.x; xr[1] = v.y; xr[2] = v.z; xr[3] = v.w;
        if (j < 8) {   // zero halo cols 0,1 and 514..519 for this row
            const int c = (j < 2) ? j : (512 + j);
            xin[row][c] = 0.f;
        }
    }
    __syncthreads();

    // ---- column pass (cooperative, all 4 kk at once)
    for (int c = t; c < XCOL; c += 512) {
        float v0 = xin[0][c], v1 = xin[1][c], v2 = xin[2][c], v3 = xin[3][c];
        float p = v0 + v3, q = v1 + v2;
        float m = v0 - v3, n = v1 - v2;
        sc[0][c] = 0.5f * (p + q);
        sc[1][c] = CA * m + CB * n;
        sc[2][c] = 0.5f * (p - q);
        sc[3][c] = CB * m - CA * n;
    }
    __syncthreads();

    // ---- row pass: group kk = t>>7 handles planes kk*4 .. kk*4+3
    const int kk = t >> 7, tt = t & 127;
    float w[12];
    {
        const float4* __restrict__ sr = reinterpret_cast<const float4*>(&sc[kk][0]);
        float4 a = sr[tt], b = sr[tt + 1], c2 = sr[tt + 2];
        w[0] = a.x;  w[1] = a.y;  w[2]  = a.z;  w[3]  = a.w;
        w[4] = b.x;  w[5] = b.y;  w[6]  = b.z;  w[7]  = b.w;
        w[8] = c2.x; w[9] = c2.y; w[10] = c2.z; w[11] = c2.w;
    }

    float* __restrict__ pb = out + (size_t)(bc * 16 + kk * 4) * PLANE
                                 + (size_t)y * WOUT + 4 * tt;
    switch (y & 3) {
        case 0: tail<0>(w, pb, tt); break;
        case 1: tail<1>(w, pb, tt); break;
        case 2: tail<2>(w, pb, tt); break;
        default: tail<3>(w, pb, tt); break;
    }
}

extern "C" void kernel_launch(void* const* d_in, const int* in_sizes, int n_in,
                              void* d_out, int out_size) {
    const float* x = (const float*)d_in[0];
    float* out     = (float*)d_out;
    (void)in_sizes; (void)n_in; (void)out_size;

    dim3 grid(HOUT, 8 * 3);   // (513, 24)
    dim3 block(512);
    dct_layer_kernel<<<grid, block>>>(x, out);
}

// round 6
// speedup vs baseline: 1.5846x; 1.0936x over previous
#include <cuda_runtime.h>
#include <cstdint>

// DCT_Layer: grouped conv, fixed separable 4x4 DCT basis, pad=2, min(|v|,8).
// x: (8,3,512,512) f32 -> out: (8,48,513,513) f32
//
// Block = 512 threads = 4 groups of 128; group kk owns planes kk*4+ll.
// 4 output rows per block (y0 multiple of 4 -> all store shifts compile-time).
//   A[0]={.5,.5,.5,.5}; A[1]={a,b,-b,-a}; A[2]={.5,-.5,-.5,.5}; A[3]={b,-a,a,-b}

#define HIN   512
#define WIN   512
#define HOUT  513
#define WOUT  513
#define PLANE (HOUT * WOUT)   // 263169 (== 1 mod 4)
#define XCOL  520             // s-cols 0..519; input col = s-col - 2
#define CA 0.65328148243818826f
#define CB 0.27059805007309851f

__constant__ float c_A[4][4] = {
    { 0.5f,  0.5f,  0.5f,  0.5f },
    {  CA,    CB,   -CB,   -CA  },
    { 0.5f, -0.5f, -0.5f,  0.5f },
    {  CB,   -CA,    CA,   -CB  }
};

__device__ __forceinline__ float t8(float v) { return fminf(fabsf(v), 8.0f); }

// 4-tap row DCT of window w at offset c (compile-time after unroll)
template<int LL>
__device__ __forceinline__ float rowdct(const float* __restrict__ w, int c) {
    if (LL == 0) return 0.5f * ((w[c] + w[c+1]) + (w[c+2] + w[c+3]));
    if (LL == 1) return CA * (w[c] - w[c+3]) + CB * (w[c+1] - w[c+2]);
    if (LL == 2) return 0.5f * ((w[c] + w[c+3]) - (w[c+1] + w[c+2]));
    return CB * (w[c] - w[c+3]) - CA * (w[c+1] - w[c+2]);
}

// One plane row: aligned float4 streaming store + edge columns.
// pl = plane base + y*513 + 4*tt; thread tt's window = s-cols 4tt..4tt+11.
template<int SH, int LL>
__device__ __forceinline__ void plane_out(const float* __restrict__ w,
                                          float* __restrict__ pl, int tt) {
    float4 v;
    v.x = t8(rowdct<LL>(w, SH + 0));
    v.y = t8(rowdct<LL>(w, SH + 1));
    v.z = t8(rowdct<LL>(w, SH + 2));
    v.w = t8(rowdct<LL>(w, SH + 3));
    if (SH <= 1 || tt < 127)
        __stcs(reinterpret_cast<float4*>(pl + SH), v);

    if (SH > 0 && tt == 0) {                 // left edge cols 0..SH-1
#pragma unroll
        for (int c = 0; c < SH; c++)
            pl[c] = t8(rowdct<LL>(w, c));
    }
    constexpr int NP = (WOUT - SH) >> 2;
    constexpr int RS = SH + 4 * NP;
    if (RS < WOUT && tt == 127) {            // right edge cols RS..512
#pragma unroll
        for (int c = RS; c < WOUT; c++)
            pl[c - 508] = t8(rowdct<LL>(w, c - 508));
    }
}

// 4 planes of one kk for output row with (y % 4) == R
template<int R>
__device__ __forceinline__ void do_row(const float* __restrict__ w,
                                       float* __restrict__ pb, int tt) {
    plane_out<(4 - ((R + 0) & 3)) & 3, 0>(w, pb,                     tt);
    plane_out<(4 - ((R + 1) & 3)) & 3, 1>(w, pb + 1 * (size_t)PLANE, tt);
    plane_out<(4 - ((R + 2) & 3)) & 3, 2>(w, pb + 2 * (size_t)PLANE, tt);
    plane_out<(4 - ((R + 3) & 3)) & 3, 3>(w, pb + 3 * (size_t)PLANE, tt);
}

__global__ __launch_bounds__(512, 3)
void dct_layer_kernel(const float* __restrict__ x, float* __restrict__ out) {
    const int y0 = blockIdx.x * 4;   // 0,4,...,512
    const int bc = blockIdx.y;       // 0..23
    const int t  = threadIdx.x;

    __shared__ float xin[7][XCOL];   // input rows y0-2 .. y0+4, pitch 2080B

    const float* __restrict__ xp = x + (size_t)bc * (HIN * WIN);

    // ---- staging: 7 rows x 128 float4 = 896 predicated LDG.128
#pragma unroll
    for (int s = 0; s < 2; s++) {
        const int idx = t + s * 512;
        if (idx < 7 * 128) {
            const int row = idx >> 7, j = idx & 127;
            const int iy = y0 - 2 + row;
            float4 v = make_float4(0.f, 0.f, 0.f, 0.f);
            if ((unsigned)iy < (unsigned)HIN)
                v = *reinterpret_cast<const float4*>(xp + iy * WIN + 4 * j);
            float* xr = &xin[row][2 + 4 * j];
            xr[0] = v.x; xr[1] = v.y; xr[2] = v.z; xr[3] = v.w;
            if (j < 8)   // zero halo cols 0,1,514..519 of this row
                xin[row][(j < 2) ? j : (512 + j)] = 0.f;
        }
    }
    __syncthreads();

    const int kk = t >> 7, tt = t & 127;
    const float k0 = c_A[kk][0], k1 = c_A[kk][1], k2 = c_A[kk][2], k3 = c_A[kk][3];

    float* __restrict__ pb = out + (size_t)(bc * 16 + kk * 4) * PLANE
                                 + (size_t)y0 * WOUT + 4 * tt;

    // ---- 4 output rows; column DCT built in registers from xin
#pragma unroll
    for (int r = 0; r < 4; r++) {
        if (y0 + r < HOUT) {
            float acc[12];
#pragma unroll
            for (int i = 0; i < 4; i++) {
                const float4* __restrict__ s4 =
                    reinterpret_cast<const float4*>(&xin[r + i][0]);
                float4 a = s4[tt], b = s4[tt + 1], c = s4[tt + 2];
                float w[12] = { a.x, a.y, a.z, a.w,
                                b.x, b.y, b.z, b.w,
                                c.x, c.y, c.z, c.w };
                const float kc = (i == 0) ? k0 : (i == 1) ? k1 : (i == 2) ? k2 : k3;
                if (i == 0) {
#pragma unroll
                    for (int j = 0; j < 12; j++) acc[j] = kc * w[j];
                } else {
#pragma unroll
                    for (int j = 0; j < 12; j++) acc[j] = fmaf(kc, w[j], acc[j]);
                }
            }
            float* __restrict__ pr = pb + (size_t)r * WOUT;
            switch (r) {            // r is a literal under unroll
                case 0: do_row<0>(acc, pr, tt); break;
                case 1: do_row<1>(acc, pr, tt); break;
                case 2: do_row<2>(acc, pr, tt); break;
                default: do_row<3>(acc, pr, tt); break;
            }
        }
    }
}

extern "C" void kernel_launch(void* const* d_in, const int* in_sizes, int n_in,
                              void* d_out, int out_size) {
    const float* x = (const float*)d_in[0];
    float* out     = (float*)d_out;
    (void)in_sizes; (void)n_in; (void)out_size;

    dim3 grid((HOUT + 3) / 4, 8 * 3);   // (129, 24)
    dim3 block(512);
    dct_layer_kernel<<<grid, block>>>(x, out);
}